// round 12
// baseline (speedup 1.0000x reference)
#include <cuda_runtime.h>
#include <cuda_fp16.h>
#include <mma.h>
#include <math.h>
#include <cstdint>

using namespace nvcuda;

__device__ __forceinline__ float sigf(float x) { return 1.f / (1.f + expf(-x)); }

// ================= scratch =================
__device__ __align__(256) __half g_hiddenh[200000 * 128];
__device__ __align__(256) __half g_W1a16[144 * 256];      // K padded 129->144
__device__ __align__(256) __half g_W1b16[256 * 256];
__device__ __align__(256) __half g_Wih16[256 * 1024];     // gate-interleaved cols
__device__ __align__(256) __half g_Whh16[256 * 1024];     // gate-interleaved cols
__device__ __align__(256) float  g_bsum[1024];            // permuted b_ih+b_hh
__device__ __align__(256) __half g_W3a16[256 * 128];
__device__ __align__(256) __half g_Wf16[128 * 192];       // folded W3b*W2b^T | W3b*b2b
__device__ __align__(256) float  g_bf[192];               // folded bias
__device__ __align__(256) __half g_h016[1024 * 256];
__device__ __align__(256) __half g_pre16[1024 * 144];
__device__ __align__(256) __half g_t1h[1024 * 256];
__device__ __align__(256) __half g_embh[1024 * 256];
__device__ __align__(256) __half g_h1h[1024 * 256];
__device__ __align__(256) __half g_t3h[1024 * 128];
__device__ __align__(256) float  g_v192[1024 * 192];      // v | c | pad

// gate-interleave: old col = g*256+h  ->  new col = (h>>4)*64 + g*16 + (h&15)
__device__ __forceinline__ int gate_perm(int col) {
    int g = col >> 8, h = col & 255;
    return ((h >> 4) << 6) + (g << 4) + (h & 15);
}

// ================= one-time fp16 conversion (weights permuted) =================
// 929792 + 1024 elems -> grid 3636 x 256
__global__ void prep16(const float* __restrict__ W1a, const float* __restrict__ W1b,
                       const float* __restrict__ Wih, const float* __restrict__ Whh,
                       const float* __restrict__ W3a, const float* __restrict__ W3b,
                       const float* __restrict__ h0,
                       const float* __restrict__ b_ih, const float* __restrict__ b_hh)
{
    int i = blockIdx.x * 256 + threadIdx.x;
    if (i < 36864) {
        int r = i >> 8, c = i & 255;
        g_W1a16[i] = (r < 129) ? __float2half_rn(W1a[r * 256 + c]) : __half(0);
        return;
    }
    i -= 36864;
    if (i < 65536)  { g_W1b16[i] = __float2half_rn(W1b[i]); return; }
    i -= 65536;
    if (i < 262144) {
        int r = i >> 10, c = i & 1023;
        g_Wih16[r * 1024 + gate_perm(c)] = __float2half_rn(Wih[i]);
        return;
    }
    i -= 262144;
    if (i < 262144) {
        int r = i >> 10, c = i & 1023;
        g_Whh16[r * 1024 + gate_perm(c)] = __float2half_rn(Whh[i]);
        return;
    }
    i -= 262144;
    if (i < 32768)  { g_W3a16[i] = __float2half_rn(W3a[i]); return; }
    i -= 32768;
    if (i < 262144) { g_h016[i] = __float2half_rn(h0[i]); return; }
    i -= 262144;
    if (i < 1024) {   // permuted bias sum: i is NEW col; invert mapping
        int tile = i >> 6, rem = i & 63, g = rem >> 4, hloc = rem & 15;
        int old = g * 256 + tile * 16 + hloc;
        g_bsum[i] = b_ih[old] + b_hh[old];
        return;
    }
}

// ================= fold W3b/W2b/b2b/b3b: Wf[128][192], bf[192] =================
// grid 97 x 256
__global__ void prep_fold(const float* __restrict__ W3b, const float* __restrict__ W2b,
                          const float* __restrict__ b2b, const float* __restrict__ b3b)
{
    int id = blockIdx.x * 256 + threadIdx.x;
    if (id < 128 * 192) {
        int k = id / 192, t = id - k * 192;
        float s = 0.f;
        if (t < 128) {
#pragma unroll 16
            for (int j = 0; j < 64; ++j) s += W3b[k * 64 + j] * W2b[t * 64 + j];
        } else if (t == 128) {
#pragma unroll 16
            for (int j = 0; j < 64; ++j) s += W3b[k * 64 + j] * b2b[j];
        }
        g_Wf16[id] = __float2half_rn(s);
        return;
    }
    id -= 128 * 192;
    if (id < 192) {
        float s = 0.f;
        if (id < 128) {
#pragma unroll 16
            for (int j = 0; j < 64; ++j) s += W2b[id * 64 + j] * b3b[j];
        } else if (id == 128) {
#pragma unroll 16
            for (int j = 0; j < 64; ++j) s += b3b[j] * b2b[j];
        }
        g_bf[id] = s;
    }
}

// ================= gather MLP1 input -> fp16 padded [1024][144] =================
__global__ void gather16(const float* __restrict__ node_emb,
                         const int* __restrict__ a0, const int* __restrict__ a1,
                         const float* __restrict__ states2)
{
    int b = blockIdx.x;
    int t = threadIdx.x;  // 144
    float v;
    if (t < 64)        v = node_emb[(size_t)a0[b] * 64 + t];
    else if (t < 128)  v = node_emb[(size_t)a1[b] * 64 + (t - 64)];
    else if (t == 128) v = states2[b] * (1.0f / 200.0f);
    else               v = 0.f;
    g_pre16[b * 144 + t] = __float2half_rn(v);
}

// ================= hidden precompute: wmma fp16, fp16 output =================
#define A_LD 72
#define B_LD 136
#define E_LD 68
#define H_SMEM_BYTES (128 * A_LD * 2 + 64 * B_LD * 2)

__global__ __launch_bounds__(256) void hidden_wmma(
    const float* __restrict__ rel, const float* __restrict__ W2a,
    const float* __restrict__ b2a, __half* __restrict__ hidden)
{
    extern __shared__ char smem[];
    __half* As = (__half*)smem;
    __half* Bs = (__half*)(smem + 128 * A_LD * 2);
    float*  Es = (float*)smem;

    const int tid = threadIdx.x;
    const int wid = tid >> 5;
    const int m0 = blockIdx.x * 128;

#pragma unroll
    for (int e = tid; e < 128 * 32; e += 256) {
        int row = e >> 5, c2 = (e & 31) << 1;
        int gr = m0 + row; if (gr > 199999) gr = 199999;
        float2 v = *(const float2*)(rel + (size_t)gr * 64 + c2);
        As[row * A_LD + c2]     = __float2half_rn(v.x);
        As[row * A_LD + c2 + 1] = __float2half_rn(v.y);
    }
#pragma unroll
    for (int e = tid; e < 64 * 64; e += 256) {
        int k = e >> 6, c2 = (e & 63) << 1;
        float2 v = *(const float2*)(W2a + (size_t)k * 128 + c2);
        Bs[k * B_LD + c2]     = __float2half_rn(v.x);
        Bs[k * B_LD + c2 + 1] = __float2half_rn(v.y);
    }
    __syncthreads();

    wmma::fragment<wmma::accumulator, 16, 16, 16, float> acc[8];
#pragma unroll
    for (int j = 0; j < 8; ++j) wmma::fill_fragment(acc[j], 0.0f);
#pragma unroll
    for (int k = 0; k < 4; ++k) {
        wmma::fragment<wmma::matrix_a, 16, 16, 16, __half, wmma::row_major> a;
        wmma::load_matrix_sync(a, As + wid * 16 * A_LD + k * 16, A_LD);
#pragma unroll
        for (int j = 0; j < 8; ++j) {
            wmma::fragment<wmma::matrix_b, 16, 16, 16, __half, wmma::row_major> b;
            wmma::load_matrix_sync(b, Bs + k * 16 * B_LD + j * 16, B_LD);
            wmma::mma_sync(acc[j], a, b, acc[j]);
        }
    }

#pragma unroll
    for (int p = 0; p < 2; ++p) {
        __syncthreads();
#pragma unroll
        for (int jj = 0; jj < 4; ++jj)
            wmma::store_matrix_sync(Es + wid * 16 * E_LD + jj * 16, acc[p * 4 + jj],
                                    E_LD, wmma::mem_row_major);
        __syncthreads();
#pragma unroll
        for (int e = tid; e < 128 * 16; e += 256) {
            int row = e >> 4, c4 = (e & 15) << 2;
            int gr = m0 + row;
            if (gr < 200000) {
                int gc = p * 64 + c4;
                float ox = fmaxf(Es[row * E_LD + c4]     + b2a[gc],     0.f);
                float oy = fmaxf(Es[row * E_LD + c4 + 1] + b2a[gc + 1], 0.f);
                float oz = fmaxf(Es[row * E_LD + c4 + 2] + b2a[gc + 2], 0.f);
                float ow = fmaxf(Es[row * E_LD + c4 + 3] + b2a[gc + 3], 0.f);
                __half2 p0 = __floats2half2_rn(ox, oy);
                __half2 p1 = __floats2half2_rn(oz, ow);
                __half2* dst = (__half2*)(hidden + (size_t)gr * 128 + gc);
                dst[0] = p0; dst[1] = p1;
            }
        }
    }
}

// ================= chain GEMM: fp16 in, pure-copy smem staging =================
// Tile 32x64, 8 warps, 1 acc each. lstm_mode: gate-interleaved epilogue -> h1/c1.
#define S_ALD 264
#define S_BLD 72
#define S_ELD 72
#define S_SMEM (32 * S_ALD * 2 + 256 * S_BLD * 2)   // 53760

__global__ __launch_bounds__(256) void gemm16s(
    const __half* __restrict__ A, int lda, int K, const __half* __restrict__ B,
    const __half* __restrict__ A2, int lda2, int K2, const __half* __restrict__ B2,
    const float* __restrict__ bias,
    float* __restrict__ Cf, __half* __restrict__ Ch, int Nt, int relu,
    int lstm_mode, const float* __restrict__ c0, float* __restrict__ out,
    __half* __restrict__ h1h)
{
    extern __shared__ char sm[];
    __half* Ah = (__half*)sm;
    __half* Bh = (__half*)(sm + 32 * S_ALD * 2);
    float*  Ef = (float*)sm;

    const int tid = threadIdx.x;
    const int wid = tid >> 5;
    const int wr = wid & 1;
    const int wc = wid >> 1;
    const int m0 = blockIdx.x * 32, n0 = blockIdx.y * 64;

    wmma::fragment<wmma::accumulator, 16, 16, 16, float> acc;
    wmma::fill_fragment(acc, 0.0f);
    wmma::fragment<wmma::matrix_a, 16, 16, 16, __half, wmma::row_major> af;
    wmma::fragment<wmma::matrix_b, 16, 16, 16, __half, wmma::row_major> bf;

    const int npass = (A2 != nullptr) ? 2 : 1;
    for (int pass = 0; pass < npass; ++pass) {
        const __half* Ap = (pass == 0) ? A : A2;
        const __half* Bp = (pass == 0) ? B : B2;
        const int Kc  = (pass == 0) ? K : K2;
        const int ldc = (pass == 0) ? lda : lda2;

        if (pass) __syncthreads();

        {   // stage A: 32 rows x Kc halves (uint4 = 8 halves)
            const int k8 = Kc >> 3;
            for (int e = tid; e < 32 * k8; e += 256) {
                int r = e / k8, c8 = (e - r * k8) << 3;
                *(uint4*)&Ah[r * S_ALD + c8] =
                    *(const uint4*)(Ap + (size_t)(m0 + r) * ldc + c8);
            }
        }
        for (int e = tid; e < (Kc << 3); e += 256) {   // stage B: Kc x 64
            int r = e >> 3, c8 = (e & 7) << 3;
            *(uint4*)&Bh[r * S_BLD + c8] =
                *(const uint4*)(Bp + (size_t)r * Nt + n0 + c8);
        }
        __syncthreads();

        const int nk = Kc >> 4;
        for (int kc = 0; kc < nk; ++kc) {
            wmma::load_matrix_sync(af, Ah + wr * 16 * S_ALD + kc * 16, S_ALD);
            wmma::load_matrix_sync(bf, Bh + (kc * 16) * S_BLD + wc * 16, S_BLD);
            wmma::mma_sync(acc, af, bf, acc);
        }
    }

    __syncthreads();
    wmma::store_matrix_sync(Ef + (wr * 16) * S_ELD + wc * 16, acc, S_ELD, wmma::mem_row_major);
    __syncthreads();

    if (lstm_mode) {
        // tile = 32 rows x (16 h x 4 gates). h = (n0/4) + hloc.
        const int hbase = n0 >> 2;
        for (int e = tid; e < 32 * 16; e += 256) {
            int r = e >> 4, hloc = e & 15;
            float gi = Ef[r * S_ELD +      hloc] + bias[n0 +      hloc];
            float gf = Ef[r * S_ELD + 16 + hloc] + bias[n0 + 16 + hloc];
            float gg = Ef[r * S_ELD + 32 + hloc] + bias[n0 + 32 + hloc];
            float go = Ef[r * S_ELD + 48 + hloc] + bias[n0 + 48 + hloc];
            int idx = (m0 + r) * 256 + hbase + hloc;
            float c  = c0[idx];
            float cn = sigf(gf) * c + sigf(gi) * tanhf(gg);
            float hn = sigf(go) * tanhf(cn);
            out[524288 + idx]          = hn;
            out[524288 + 262144 + idx] = cn;
            h1h[idx] = __float2half_rn(hn);
        }
        return;
    }

    for (int e = tid; e < 32 * 16; e += 256) {
        int r = e >> 4, c4 = (e & 15) << 2;
        int gm = m0 + r, gn = n0 + c4;
        float4 x = *(const float4*)&Ef[r * S_ELD + c4];
        if (bias) { x.x += bias[gn]; x.y += bias[gn+1]; x.z += bias[gn+2]; x.w += bias[gn+3]; }
        if (relu) {
            x.x = fmaxf(x.x, 0.f); x.y = fmaxf(x.y, 0.f);
            x.z = fmaxf(x.z, 0.f); x.w = fmaxf(x.w, 0.f);
        }
        if (Cf) *(float4*)(Cf + (size_t)gm * Nt + gn) = x;
        if (Ch) {
            __half2 h0v = __floats2half2_rn(x.x, x.y);
            __half2 h1v = __floats2half2_rn(x.z, x.w);
            __half2* d = (__half2*)(Ch + (size_t)gm * Nt + gn);
            d[0] = h0v; d[1] = h1v;
        }
    }
}

// ================= scoring (fp16 hidden rows; split-K grid) =================
__global__ __launch_bounds__(256) void score_kernel(
    const int* __restrict__ cand, const __half* __restrict__ hidden,
    const float* __restrict__ v, float* __restrict__ out)
{
    int b = blockIdx.x;
    int k0 = blockIdx.y << 8;     // 0 or 256
    int l = threadIdx.x & 7;
    int grp = threadIdx.x >> 3;

    float vr[16];
#pragma unroll
    for (int j = 0; j < 8; ++j) vr[j]     = v[b * 192 + l * 8 + j];
#pragma unroll
    for (int j = 0; j < 8; ++j) vr[8 + j] = v[b * 192 + 64 + l * 8 + j];
    float cb = v[b * 192 + 128];

#pragma unroll
    for (int i = 0; i < 8; ++i) {
        int k = k0 + grp + i * 32;
        int idx = cand[b * 512 + k];
        const uint4* row = (const uint4*)(hidden + (size_t)idx * 128);
        uint4 q0 = row[l];
        uint4 q1 = row[8 + l];
        float acc = 0.f;
        {
            float2 f;
            f = __half22float2(*(__half2*)&q0.x); acc += f.x * vr[0] + f.y * vr[1];
            f = __half22float2(*(__half2*)&q0.y); acc += f.x * vr[2] + f.y * vr[3];
            f = __half22float2(*(__half2*)&q0.z); acc += f.x * vr[4] + f.y * vr[5];
            f = __half22float2(*(__half2*)&q0.w); acc += f.x * vr[6] + f.y * vr[7];
            f = __half22float2(*(__half2*)&q1.x); acc += f.x * vr[8] + f.y * vr[9];
            f = __half22float2(*(__half2*)&q1.y); acc += f.x * vr[10] + f.y * vr[11];
            f = __half22float2(*(__half2*)&q1.z); acc += f.x * vr[12] + f.y * vr[13];
            f = __half22float2(*(__half2*)&q1.w); acc += f.x * vr[14] + f.y * vr[15];
        }
        acc += __shfl_down_sync(0xffffffffu, acc, 4);
        acc += __shfl_down_sync(0xffffffffu, acc, 2);
        acc += __shfl_down_sync(0xffffffffu, acc, 1);
        if (l == 0) out[b * 512 + k] = (acc + cb) * 0.125f;
    }
}

// ================= launch (fork: gather+hidden ∥ prep+chain; join at score) =====
extern "C" void kernel_launch(void* const* d_in, const int* in_sizes, int n_in,
                              void* d_out, int out_size)
{
    const float* states2  = (const float*)d_in[0];
    const float* h0       = (const float*)d_in[1];
    const float* c0       = (const float*)d_in[2];
    const int*   actions0 = (const int*)d_in[3];
    const int*   actions1 = (const int*)d_in[4];
    const int*   cand     = (const int*)d_in[5];
    const float* node_emb = (const float*)d_in[6];
    const float* rel_emb  = (const float*)d_in[7];
    const float* W1a = (const float*)d_in[8];
    const float* b1a = (const float*)d_in[9];
    const float* W1b = (const float*)d_in[10];
    const float* b1b = (const float*)d_in[11];
    const float* W2a = (const float*)d_in[12];
    const float* b2a = (const float*)d_in[13];
    const float* W2b = (const float*)d_in[14];
    const float* b2b = (const float*)d_in[15];
    const float* W3a = (const float*)d_in[16];
    const float* b3a = (const float*)d_in[17];
    const float* W3b = (const float*)d_in[18];
    const float* b3b = (const float*)d_in[19];
    const float* W_ih = (const float*)d_in[20];
    const float* W_hh = (const float*)d_in[21];
    const float* b_ih = (const float*)d_in[22];
    const float* b_hh = (const float*)d_in[23];
    float* out = (float*)d_out;

    __half *p_hiddenh, *p_W1a16, *p_W1b16, *p_Wih16, *p_Whh16, *p_W3a16, *p_Wf16;
    __half *p_h016, *p_pre16, *p_t1h, *p_embh, *p_h1h, *p_t3h;
    float *p_bsum, *p_bf, *p_v192;
    cudaGetSymbolAddress((void**)&p_hiddenh, g_hiddenh);
    cudaGetSymbolAddress((void**)&p_W1a16, g_W1a16);
    cudaGetSymbolAddress((void**)&p_W1b16, g_W1b16);
    cudaGetSymbolAddress((void**)&p_Wih16, g_Wih16);
    cudaGetSymbolAddress((void**)&p_Whh16, g_Whh16);
    cudaGetSymbolAddress((void**)&p_W3a16, g_W3a16);
    cudaGetSymbolAddress((void**)&p_Wf16,  g_Wf16);
    cudaGetSymbolAddress((void**)&p_h016,  g_h016);
    cudaGetSymbolAddress((void**)&p_pre16, g_pre16);
    cudaGetSymbolAddress((void**)&p_t1h,   g_t1h);
    cudaGetSymbolAddress((void**)&p_embh,  g_embh);
    cudaGetSymbolAddress((void**)&p_h1h,   g_h1h);
    cudaGetSymbolAddress((void**)&p_t3h,   g_t3h);
    cudaGetSymbolAddress((void**)&p_bsum,  g_bsum);
    cudaGetSymbolAddress((void**)&p_bf,    g_bf);
    cudaGetSymbolAddress((void**)&p_v192,  g_v192);

    cudaFuncSetAttribute(gemm16s, cudaFuncAttributeMaxDynamicSharedMemorySize, S_SMEM);

    cudaStream_t s1;
    cudaStreamCreateWithFlags(&s1, cudaStreamNonBlocking);
    cudaEvent_t eFork, eGather, eJoin;
    cudaEventCreateWithFlags(&eFork,   cudaEventDisableTiming);
    cudaEventCreateWithFlags(&eGather, cudaEventDisableTiming);
    cudaEventCreateWithFlags(&eJoin,   cudaEventDisableTiming);

    cudaEventRecord(eFork, 0);
    cudaStreamWaitEvent(s1, eFork, 0);

    // branch A (s1): gather (concurrent with prep16) then hidden table
    gather16<<<1024, 144, 0, s1>>>(node_emb, actions0, actions1, states2);
    cudaEventRecord(eGather, s1);
    hidden_wmma<<<1563, 256, H_SMEM_BYTES, s1>>>(rel_emb, W2a, b2a, p_hiddenh);
    cudaEventRecord(eJoin, s1);

    // branch B (capture stream): prep + chain
    prep16<<<3636, 256>>>(W1a, W1b, W_ih, W_hh, W3a, W3b, h0, b_ih, b_hh);
    prep_fold<<<97, 256>>>(W3b, W2b, b2b, b3b);
    cudaStreamWaitEvent(0, eGather, 0);
    // t1 = relu(pre @ W1a + b1a)  [1024,256] K=144
    gemm16s<<<dim3(32, 4), 256, S_SMEM>>>(p_pre16, 144, 144, p_W1a16,
                                          nullptr, 0, 0, nullptr,
                                          b1a, nullptr, p_t1h, 256, 1,
                                          0, nullptr, nullptr, nullptr);
    // emb = t1 @ W1b + b1b       [1024,256] K=256
    gemm16s<<<dim3(32, 4), 256, S_SMEM>>>(p_t1h, 256, 256, p_W1b16,
                                          nullptr, 0, 0, nullptr,
                                          b1b, nullptr, p_embh, 256, 0,
                                          0, nullptr, nullptr, nullptr);
    // gates(+LSTM) = emb @ Wih + h0 @ Whh (gate-interleaved) -> h1,c1,h1h
    gemm16s<<<dim3(32, 16), 256, S_SMEM>>>(p_embh, 256, 256, p_Wih16,
                                           p_h016, 256, 256, p_Whh16,
                                           p_bsum, nullptr, nullptr, 1024, 0,
                                           1, c0, out, p_h1h);
    // t3 = relu(h1 @ W3a + b3a)  [1024,128] K=256
    gemm16s<<<dim3(32, 2), 256, S_SMEM>>>(p_h1h, 256, 256, p_W3a16,
                                          nullptr, 0, 0, nullptr,
                                          b3a, nullptr, p_t3h, 128, 1,
                                          0, nullptr, nullptr, nullptr);
    // v|c = t3 @ Wf + bf          [1024,192] K=128
    gemm16s<<<dim3(32, 3), 256, S_SMEM>>>(p_t3h, 128, 128, p_Wf16,
                                          nullptr, 0, 0, nullptr,
                                          p_bf, p_v192, nullptr, 192, 0,
                                          0, nullptr, nullptr, nullptr);

    // join
    cudaStreamWaitEvent(0, eJoin, 0);
    score_kernel<<<dim3(1024, 2), 256>>>(cand, p_hiddenh, p_v192, out);
}

// round 14
// speedup vs baseline: 1.6983x; 1.6983x over previous
#include <cuda_runtime.h>
#include <cuda_fp16.h>
#include <mma.h>
#include <math.h>
#include <cstdint>

using namespace nvcuda;

__device__ __forceinline__ float sigf(float x) { return 1.f / (1.f + expf(-x)); }

// ================= scratch =================
__device__ __align__(256) __half g_hiddenh[200000 * 128];
__device__ __align__(256) __half g_W1a16[144 * 256];      // K padded 129->144
__device__ __align__(256) __half g_W1b16[256 * 256];
__device__ __align__(256) __half g_Wih16[256 * 1024];     // gate-interleaved cols
__device__ __align__(256) __half g_Whh16[256 * 1024];     // gate-interleaved cols
__device__ __align__(256) float  g_bsum[1024];            // permuted b_ih+b_hh
__device__ __align__(256) __half g_W3a16[256 * 128];
__device__ __align__(256) __half g_Wf16[128 * 192];       // folded W3b*W2b^T | W3b*b2b
__device__ __align__(256) float  g_bf[192];               // folded bias
__device__ __align__(256) __half g_h016[1024 * 256];
__device__ __align__(256) __half g_pre16[1024 * 144];
__device__ __align__(256) __half g_t1h[1024 * 256];
__device__ __align__(256) __half g_embh[1024 * 256];
__device__ __align__(256) __half g_h1h[1024 * 256];
__device__ __align__(256) __half g_t3h[1024 * 128];
__device__ __align__(256) float  g_v192[1024 * 192];      // v | c | pad

// gate-interleave: old col = g*256+h  ->  new col = (h>>4)*64 + g*16 + (h&15)
__device__ __forceinline__ int gate_perm(int col) {
    int g = col >> 8, h = col & 255;
    return ((h >> 4) << 6) + (g << 4) + (h & 15);
}

// ================= one-time fp16 conversion (weights permuted) =================
// 929792 + 1024 elems -> grid 3636 x 256
__global__ void prep16(const float* __restrict__ W1a, const float* __restrict__ W1b,
                       const float* __restrict__ Wih, const float* __restrict__ Whh,
                       const float* __restrict__ W3a, const float* __restrict__ W3b,
                       const float* __restrict__ h0,
                       const float* __restrict__ b_ih, const float* __restrict__ b_hh)
{
    int i = blockIdx.x * 256 + threadIdx.x;
    if (i < 36864) {
        int r = i >> 8, c = i & 255;
        g_W1a16[i] = (r < 129) ? __float2half_rn(W1a[r * 256 + c]) : __half(0);
        return;
    }
    i -= 36864;
    if (i < 65536)  { g_W1b16[i] = __float2half_rn(W1b[i]); return; }
    i -= 65536;
    if (i < 262144) {
        int r = i >> 10, c = i & 1023;
        g_Wih16[r * 1024 + gate_perm(c)] = __float2half_rn(Wih[i]);
        return;
    }
    i -= 262144;
    if (i < 262144) {
        int r = i >> 10, c = i & 1023;
        g_Whh16[r * 1024 + gate_perm(c)] = __float2half_rn(Whh[i]);
        return;
    }
    i -= 262144;
    if (i < 32768)  { g_W3a16[i] = __float2half_rn(W3a[i]); return; }
    i -= 32768;
    if (i < 262144) { g_h016[i] = __float2half_rn(h0[i]); return; }
    i -= 262144;
    if (i < 1024) {   // permuted bias sum: i is NEW col; invert mapping
        int tile = i >> 6, rem = i & 63, g = rem >> 4, hloc = rem & 15;
        int old = g * 256 + tile * 16 + hloc;
        g_bsum[i] = b_ih[old] + b_hh[old];
        return;
    }
}

// ================= fold W3b/W2b/b2b/b3b (latency-optimized) ====================
// grid 97 x 256; float4 loads, 4 accumulators (MLP ~8)
__global__ void prep_fold(const float* __restrict__ W3b, const float* __restrict__ W2b,
                          const float* __restrict__ b2b, const float* __restrict__ b3b)
{
    int id = blockIdx.x * 256 + threadIdx.x;
    if (id < 128 * 192) {
        int k = id / 192, t = id - k * 192;
        float s = 0.f;
        if (t < 128) {
            float s0 = 0.f, s1 = 0.f, s2 = 0.f, s3 = 0.f;
#pragma unroll
            for (int j = 0; j < 64; j += 8) {
                float4 a0 = *(const float4*)(W3b + k * 64 + j);
                float4 a1 = *(const float4*)(W3b + k * 64 + j + 4);
                float4 b0 = *(const float4*)(W2b + t * 64 + j);
                float4 b1 = *(const float4*)(W2b + t * 64 + j + 4);
                s0 += a0.x * b0.x + a0.y * b0.y;
                s1 += a0.z * b0.z + a0.w * b0.w;
                s2 += a1.x * b1.x + a1.y * b1.y;
                s3 += a1.z * b1.z + a1.w * b1.w;
            }
            s = (s0 + s1) + (s2 + s3);
        } else if (t == 128) {
            float s0 = 0.f, s1 = 0.f;
#pragma unroll
            for (int j = 0; j < 64; j += 4) {
                float4 a = *(const float4*)(W3b + k * 64 + j);
                float4 b = *(const float4*)(b2b + j);
                s0 += a.x * b.x + a.y * b.y;
                s1 += a.z * b.z + a.w * b.w;
            }
            s = s0 + s1;
        }
        g_Wf16[id] = __float2half_rn(s);
        return;
    }
    id -= 128 * 192;
    if (id < 192) {
        float s = 0.f;
        if (id < 128) {
            float s0 = 0.f, s1 = 0.f;
#pragma unroll
            for (int j = 0; j < 64; j += 4) {
                float4 a = *(const float4*)(W2b + id * 64 + j);
                float4 b = *(const float4*)(b3b + j);
                s0 += a.x * b.x + a.y * b.y;
                s1 += a.z * b.z + a.w * b.w;
            }
            s = s0 + s1;
        } else if (id == 128) {
            float s0 = 0.f, s1 = 0.f;
#pragma unroll
            for (int j = 0; j < 64; j += 4) {
                float4 a = *(const float4*)(b3b + j);
                float4 b = *(const float4*)(b2b + j);
                s0 += a.x * b.x + a.y * b.y;
                s1 += a.z * b.z + a.w * b.w;
            }
            s = s0 + s1;
        }
        g_bf[id] = s;
    }
}

// ================= gather MLP1 input -> fp16 padded [1024][144] =================
__global__ void gather16(const float* __restrict__ node_emb,
                         const int* __restrict__ a0, const int* __restrict__ a1,
                         const float* __restrict__ states2)
{
    int b = blockIdx.x;
    int t = threadIdx.x;  // 144
    float v;
    if (t < 64)        v = node_emb[(size_t)a0[b] * 64 + t];
    else if (t < 128)  v = node_emb[(size_t)a1[b] * 64 + (t - 64)];
    else if (t == 128) v = states2[b] * (1.0f / 200.0f);
    else               v = 0.f;
    g_pre16[b * 144 + t] = __float2half_rn(v);
}

// ================= hidden precompute: wmma fp16, fp16 output =================
#define A_LD 72
#define B_LD 136
#define E_LD 68
#define H_SMEM_BYTES (128 * A_LD * 2 + 64 * B_LD * 2)

__global__ __launch_bounds__(256) void hidden_wmma(
    const float* __restrict__ rel, const float* __restrict__ W2a,
    const float* __restrict__ b2a, __half* __restrict__ hidden)
{
    extern __shared__ char smem[];
    __half* As = (__half*)smem;
    __half* Bs = (__half*)(smem + 128 * A_LD * 2);
    float*  Es = (float*)smem;

    const int tid = threadIdx.x;
    const int wid = tid >> 5;
    const int m0 = blockIdx.x * 128;

#pragma unroll
    for (int e = tid; e < 128 * 32; e += 256) {
        int row = e >> 5, c2 = (e & 31) << 1;
        int gr = m0 + row; if (gr > 199999) gr = 199999;
        float2 v = *(const float2*)(rel + (size_t)gr * 64 + c2);
        As[row * A_LD + c2]     = __float2half_rn(v.x);
        As[row * A_LD + c2 + 1] = __float2half_rn(v.y);
    }
#pragma unroll
    for (int e = tid; e < 64 * 64; e += 256) {
        int k = e >> 6, c2 = (e & 63) << 1;
        float2 v = *(const float2*)(W2a + (size_t)k * 128 + c2);
        Bs[k * B_LD + c2]     = __float2half_rn(v.x);
        Bs[k * B_LD + c2 + 1] = __float2half_rn(v.y);
    }
    __syncthreads();

    wmma::fragment<wmma::accumulator, 16, 16, 16, float> acc[8];
#pragma unroll
    for (int j = 0; j < 8; ++j) wmma::fill_fragment(acc[j], 0.0f);
#pragma unroll
    for (int k = 0; k < 4; ++k) {
        wmma::fragment<wmma::matrix_a, 16, 16, 16, __half, wmma::row_major> a;
        wmma::load_matrix_sync(a, As + wid * 16 * A_LD + k * 16, A_LD);
#pragma unroll
        for (int j = 0; j < 8; ++j) {
            wmma::fragment<wmma::matrix_b, 16, 16, 16, __half, wmma::row_major> b;
            wmma::load_matrix_sync(b, Bs + k * 16 * B_LD + j * 16, B_LD);
            wmma::mma_sync(acc[j], a, b, acc[j]);
        }
    }

#pragma unroll
    for (int p = 0; p < 2; ++p) {
        __syncthreads();
#pragma unroll
        for (int jj = 0; jj < 4; ++jj)
            wmma::store_matrix_sync(Es + wid * 16 * E_LD + jj * 16, acc[p * 4 + jj],
                                    E_LD, wmma::mem_row_major);
        __syncthreads();
#pragma unroll
        for (int e = tid; e < 128 * 16; e += 256) {
            int row = e >> 4, c4 = (e & 15) << 2;
            int gr = m0 + row;
            if (gr < 200000) {
                int gc = p * 64 + c4;
                float ox = fmaxf(Es[row * E_LD + c4]     + b2a[gc],     0.f);
                float oy = fmaxf(Es[row * E_LD + c4 + 1] + b2a[gc + 1], 0.f);
                float oz = fmaxf(Es[row * E_LD + c4 + 2] + b2a[gc + 2], 0.f);
                float ow = fmaxf(Es[row * E_LD + c4 + 3] + b2a[gc + 3], 0.f);
                __half2 p0 = __floats2half2_rn(ox, oy);
                __half2 p1 = __floats2half2_rn(oz, ow);
                __half2* dst = (__half2*)(hidden + (size_t)gr * 128 + gc);
                dst[0] = p0; dst[1] = p1;
            }
        }
    }
}

// ================= chain GEMM: fp16 in, pure-copy smem staging =================
// Tile 32x64, 8 warps, 1 acc each. lstm_mode: gate-interleaved epilogue -> h1/c1.
#define S_ALD 264
#define S_BLD 72
#define S_ELD 72
#define S_SMEM (32 * S_ALD * 2 + 256 * S_BLD * 2)   // 53760

__global__ __launch_bounds__(256) void gemm16s(
    const __half* __restrict__ A, int lda, int K, const __half* __restrict__ B,
    const __half* __restrict__ A2, int lda2, int K2, const __half* __restrict__ B2,
    const float* __restrict__ bias,
    float* __restrict__ Cf, __half* __restrict__ Ch, int Nt, int relu,
    int lstm_mode, const float* __restrict__ c0, float* __restrict__ out,
    __half* __restrict__ h1h)
{
    extern __shared__ char sm[];
    __half* Ah = (__half*)sm;
    __half* Bh = (__half*)(sm + 32 * S_ALD * 2);
    float*  Ef = (float*)sm;

    const int tid = threadIdx.x;
    const int wid = tid >> 5;
    const int wr = wid & 1;
    const int wc = wid >> 1;
    const int m0 = blockIdx.x * 32, n0 = blockIdx.y * 64;

    wmma::fragment<wmma::accumulator, 16, 16, 16, float> acc;
    wmma::fill_fragment(acc, 0.0f);
    wmma::fragment<wmma::matrix_a, 16, 16, 16, __half, wmma::row_major> af;
    wmma::fragment<wmma::matrix_b, 16, 16, 16, __half, wmma::row_major> bf;

    const int npass = (A2 != nullptr) ? 2 : 1;
    for (int pass = 0; pass < npass; ++pass) {
        const __half* Ap = (pass == 0) ? A : A2;
        const __half* Bp = (pass == 0) ? B : B2;
        const int Kc  = (pass == 0) ? K : K2;
        const int ldc = (pass == 0) ? lda : lda2;

        if (pass) __syncthreads();

        {   // stage A: 32 rows x Kc halves (uint4 = 8 halves)
            const int k8 = Kc >> 3;
            for (int e = tid; e < 32 * k8; e += 256) {
                int r = e / k8, c8 = (e - r * k8) << 3;
                *(uint4*)&Ah[r * S_ALD + c8] =
                    *(const uint4*)(Ap + (size_t)(m0 + r) * ldc + c8);
            }
        }
        for (int e = tid; e < (Kc << 3); e += 256) {   // stage B: Kc x 64
            int r = e >> 3, c8 = (e & 7) << 3;
            *(uint4*)&Bh[r * S_BLD + c8] =
                *(const uint4*)(Bp + (size_t)r * Nt + n0 + c8);
        }
        __syncthreads();

        const int nk = Kc >> 4;
        for (int kc = 0; kc < nk; ++kc) {
            wmma::load_matrix_sync(af, Ah + wr * 16 * S_ALD + kc * 16, S_ALD);
            wmma::load_matrix_sync(bf, Bh + (kc * 16) * S_BLD + wc * 16, S_BLD);
            wmma::mma_sync(acc, af, bf, acc);
        }
    }

    __syncthreads();
    wmma::store_matrix_sync(Ef + (wr * 16) * S_ELD + wc * 16, acc, S_ELD, wmma::mem_row_major);
    __syncthreads();

    if (lstm_mode) {
        // tile = 32 rows x (16 h x 4 gates). h = (n0/4) + hloc.
        const int hbase = n0 >> 2;
        for (int e = tid; e < 32 * 16; e += 256) {
            int r = e >> 4, hloc = e & 15;
            float gi = Ef[r * S_ELD +      hloc] + bias[n0 +      hloc];
            float gf = Ef[r * S_ELD + 16 + hloc] + bias[n0 + 16 + hloc];
            float gg = Ef[r * S_ELD + 32 + hloc] + bias[n0 + 32 + hloc];
            float go = Ef[r * S_ELD + 48 + hloc] + bias[n0 + 48 + hloc];
            int idx = (m0 + r) * 256 + hbase + hloc;
            float c  = c0[idx];
            float cn = sigf(gf) * c + sigf(gi) * tanhf(gg);
            float hn = sigf(go) * tanhf(cn);
            out[524288 + idx]          = hn;
            out[524288 + 262144 + idx] = cn;
            h1h[idx] = __float2half_rn(hn);
        }
        return;
    }

    for (int e = tid; e < 32 * 16; e += 256) {
        int r = e >> 4, c4 = (e & 15) << 2;
        int gm = m0 + r, gn = n0 + c4;
        float4 x = *(const float4*)&Ef[r * S_ELD + c4];
        if (bias) { x.x += bias[gn]; x.y += bias[gn+1]; x.z += bias[gn+2]; x.w += bias[gn+3]; }
        if (relu) {
            x.x = fmaxf(x.x, 0.f); x.y = fmaxf(x.y, 0.f);
            x.z = fmaxf(x.z, 0.f); x.w = fmaxf(x.w, 0.f);
        }
        if (Cf) *(float4*)(Cf + (size_t)gm * Nt + gn) = x;
        if (Ch) {
            __half2 h0v = __floats2half2_rn(x.x, x.y);
            __half2 h1v = __floats2half2_rn(x.z, x.w);
            __half2* d = (__half2*)(Ch + (size_t)gm * Nt + gn);
            d[0] = h0v; d[1] = h1v;
        }
    }
}

// ================= scoring (fp16 hidden rows; split-K grid) =================
__global__ __launch_bounds__(256) void score_kernel(
    const int* __restrict__ cand, const __half* __restrict__ hidden,
    const float* __restrict__ v, float* __restrict__ out)
{
    int b = blockIdx.x;
    int k0 = blockIdx.y << 8;     // 0 or 256
    int l = threadIdx.x & 7;
    int grp = threadIdx.x >> 3;

    float vr[16];
#pragma unroll
    for (int j = 0; j < 8; ++j) vr[j]     = v[b * 192 + l * 8 + j];
#pragma unroll
    for (int j = 0; j < 8; ++j) vr[8 + j] = v[b * 192 + 64 + l * 8 + j];
    float cb = v[b * 192 + 128];

#pragma unroll
    for (int i = 0; i < 8; ++i) {
        int k = k0 + grp + i * 32;
        int idx = cand[b * 512 + k];
        const uint4* row = (const uint4*)(hidden + (size_t)idx * 128);
        uint4 q0 = row[l];
        uint4 q1 = row[8 + l];
        float acc = 0.f;
        {
            float2 f;
            f = __half22float2(*(__half2*)&q0.x); acc += f.x * vr[0] + f.y * vr[1];
            f = __half22float2(*(__half2*)&q0.y); acc += f.x * vr[2] + f.y * vr[3];
            f = __half22float2(*(__half2*)&q0.z); acc += f.x * vr[4] + f.y * vr[5];
            f = __half22float2(*(__half2*)&q0.w); acc += f.x * vr[6] + f.y * vr[7];
            f = __half22float2(*(__half2*)&q1.x); acc += f.x * vr[8] + f.y * vr[9];
            f = __half22float2(*(__half2*)&q1.y); acc += f.x * vr[10] + f.y * vr[11];
            f = __half22float2(*(__half2*)&q1.z); acc += f.x * vr[12] + f.y * vr[13];
            f = __half22float2(*(__half2*)&q1.w); acc += f.x * vr[14] + f.y * vr[15];
        }
        acc += __shfl_down_sync(0xffffffffu, acc, 4);
        acc += __shfl_down_sync(0xffffffffu, acc, 2);
        acc += __shfl_down_sync(0xffffffffu, acc, 1);
        if (l == 0) out[b * 512 + k] = (acc + cb) * 0.125f;
    }
}

// ================= launch (R10 topology: fork hidden ∥ chain; join at score) ====
extern "C" void kernel_launch(void* const* d_in, const int* in_sizes, int n_in,
                              void* d_out, int out_size)
{
    const float* states2  = (const float*)d_in[0];
    const float* h0       = (const float*)d_in[1];
    const float* c0       = (const float*)d_in[2];
    const int*   actions0 = (const int*)d_in[3];
    const int*   actions1 = (const int*)d_in[4];
    const int*   cand     = (const int*)d_in[5];
    const float* node_emb = (const float*)d_in[6];
    const float* rel_emb  = (const float*)d_in[7];
    const float* W1a = (const float*)d_in[8];
    const float* b1a = (const float*)d_in[9];
    const float* W1b = (const float*)d_in[10];
    const float* b1b = (const float*)d_in[11];
    const float* W2a = (const float*)d_in[12];
    const float* b2a = (const float*)d_in[13];
    const float* W2b = (const float*)d_in[14];
    const float* b2b = (const float*)d_in[15];
    const float* W3a = (const float*)d_in[16];
    const float* b3a = (const float*)d_in[17];
    const float* W3b = (const float*)d_in[18];
    const float* b3b = (const float*)d_in[19];
    const float* W_ih = (const float*)d_in[20];
    const float* W_hh = (const float*)d_in[21];
    const float* b_ih = (const float*)d_in[22];
    const float* b_hh = (const float*)d_in[23];
    float* out = (float*)d_out;

    __half *p_hiddenh, *p_W1a16, *p_W1b16, *p_Wih16, *p_Whh16, *p_W3a16, *p_Wf16;
    __half *p_h016, *p_pre16, *p_t1h, *p_embh, *p_h1h, *p_t3h;
    float *p_bsum, *p_bf, *p_v192;
    cudaGetSymbolAddress((void**)&p_hiddenh, g_hiddenh);
    cudaGetSymbolAddress((void**)&p_W1a16, g_W1a16);
    cudaGetSymbolAddress((void**)&p_W1b16, g_W1b16);
    cudaGetSymbolAddress((void**)&p_Wih16, g_Wih16);
    cudaGetSymbolAddress((void**)&p_Whh16, g_Whh16);
    cudaGetSymbolAddress((void**)&p_W3a16, g_W3a16);
    cudaGetSymbolAddress((void**)&p_Wf16,  g_Wf16);
    cudaGetSymbolAddress((void**)&p_h016,  g_h016);
    cudaGetSymbolAddress((void**)&p_pre16, g_pre16);
    cudaGetSymbolAddress((void**)&p_t1h,   g_t1h);
    cudaGetSymbolAddress((void**)&p_embh,  g_embh);
    cudaGetSymbolAddress((void**)&p_h1h,   g_h1h);
    cudaGetSymbolAddress((void**)&p_t3h,   g_t3h);
    cudaGetSymbolAddress((void**)&p_bsum,  g_bsum);
    cudaGetSymbolAddress((void**)&p_bf,    g_bf);
    cudaGetSymbolAddress((void**)&p_v192,  g_v192);

    cudaFuncSetAttribute(gemm16s, cudaFuncAttributeMaxDynamicSharedMemorySize, S_SMEM);

    cudaStream_t s1;
    cudaStreamCreateWithFlags(&s1, cudaStreamNonBlocking);
    cudaEvent_t eFork, eJoin;
    cudaEventCreateWithFlags(&eFork, cudaEventDisableTiming);
    cudaEventCreateWithFlags(&eJoin, cudaEventDisableTiming);

    cudaEventRecord(eFork, 0);
    cudaStreamWaitEvent(s1, eFork, 0);

    // branch A (s1): hidden table
    hidden_wmma<<<1563, 256, H_SMEM_BYTES, s1>>>(rel_emb, W2a, b2a, p_hiddenh);
    cudaEventRecord(eJoin, s1);

    // branch B (capture stream): prep + chain
    prep16<<<3636, 256>>>(W1a, W1b, W_ih, W_hh, W3a, W3b, h0, b_ih, b_hh);
    prep_fold<<<97, 256>>>(W3b, W2b, b2b, b3b);
    gather16<<<1024, 144>>>(node_emb, actions0, actions1, states2);
    // t1 = relu(pre @ W1a + b1a)  [1024,256] K=144
    gemm16s<<<dim3(32, 4), 256, S_SMEM>>>(p_pre16, 144, 144, p_W1a16,
                                          nullptr, 0, 0, nullptr,
                                          b1a, nullptr, p_t1h, 256, 1,
                                          0, nullptr, nullptr, nullptr);
    // emb = t1 @ W1b + b1b       [1024,256] K=256
    gemm16s<<<dim3(32, 4), 256, S_SMEM>>>(p_t1h, 256, 256, p_W1b16,
                                          nullptr, 0, 0, nullptr,
                                          b1b, nullptr, p_embh, 256, 0,
                                          0, nullptr, nullptr, nullptr);
    // gates(+LSTM) = emb @ Wih + h0 @ Whh (gate-interleaved) -> h1,c1,h1h
    gemm16s<<<dim3(32, 16), 256, S_SMEM>>>(p_embh, 256, 256, p_Wih16,
                                           p_h016, 256, 256, p_Whh16,
                                           p_bsum, nullptr, nullptr, 1024, 0,
                                           1, c0, out, p_h1h);
    // t3 = relu(h1 @ W3a + b3a)  [1024,128] K=256
    gemm16s<<<dim3(32, 2), 256, S_SMEM>>>(p_h1h, 256, 256, p_W3a16,
                                          nullptr, 0, 0, nullptr,
                                          b3a, nullptr, p_t3h, 128, 1,
                                          0, nullptr, nullptr, nullptr);
    // v|c = t3 @ Wf + bf          [1024,192] K=128
    gemm16s<<<dim3(32, 3), 256, S_SMEM>>>(p_t3h, 128, 128, p_Wf16,
                                          nullptr, 0, 0, nullptr,
                                          p_bf, p_v192, nullptr, 192, 0,
                                          0, nullptr, nullptr, nullptr);

    // join
    cudaStreamWaitEvent(0, eJoin, 0);
    score_kernel<<<dim3(1024, 2), 256>>>(cand, p_hiddenh, p_v192, out);
}